// round 2
// baseline (speedup 1.0000x reference)
#include <cuda_runtime.h>
#include <cstdint>

#define EPS 1e-5f
#define NUM_GRAPHS 128

// Scratch: per-node graph id, uint8 (NUM_GRAPHS=128 fits). N=100000.
__device__ unsigned char g_batch8[131072];

// Prologue: zero output bins + compress batch_index (int32) -> uint8 table.
__global__ void prep_kernel(const int* __restrict__ batch_index,
                            float* __restrict__ out, int N) {
    int i = blockIdx.x * blockDim.x + threadIdx.x;
    if (i < NUM_GRAPHS) out[i] = 0.0f;
    if (i < N) g_batch8[i] = (unsigned char)batch_index[i];
}

__device__ __forceinline__ bool xing_test(float2 p1, float2 p2, float2 p3, float2 p4) {
    float rx = p4.x - p3.x, ry = p4.y - p3.y;
    float d1 = rx * (p1.y - p3.y) - ry * (p1.x - p3.x);
    float d2 = rx * (p2.y - p3.y) - ry * (p2.x - p3.x);
    float qx = p2.x - p1.x, qy = p2.y - p1.y;
    float d3 = qx * (p3.y - p1.y) - qy * (p3.x - p1.x);
    float d4 = qx * (p4.y - p1.y) - qy * (p4.x - p1.x);
    return (d1 * d2 < -EPS) & (d3 * d4 < -EPS);
}

// Main: grid-stride, 4 pairs per thread via int4 index loads.
__global__ void __launch_bounds__(256)
crossings_kernel(const float2* __restrict__ pos,
                 const int* __restrict__ epi,  // [2][2][P]: s1 | s2 | e1 | e2
                 float* __restrict__ out,
                 int P) {
    __shared__ float hist[NUM_GRAPHS];
    for (int i = threadIdx.x; i < NUM_GRAPHS; i += blockDim.x) hist[i] = 0.0f;
    __syncthreads();

    const int P4 = P >> 2;  // int4-vectorized count (4 pairs per element)
    const int4* __restrict__ s1v = (const int4*)(epi);
    const int4* __restrict__ s2v = (const int4*)(epi + (size_t)P);
    const int4* __restrict__ e1v = (const int4*)(epi + 2 * (size_t)P);
    const int4* __restrict__ e2v = (const int4*)(epi + 3 * (size_t)P);

    const int stride = gridDim.x * blockDim.x;

    for (int v = blockIdx.x * blockDim.x + threadIdx.x; v < P4; v += stride) {
        int4 s1 = __ldg(s1v + v);
        int4 s2 = __ldg(s2v + v);
        int4 e1 = __ldg(e1v + v);
        int4 e2 = __ldg(e2v + v);

        // Issue all 16 gathers up front for MLP.
        float2 a1 = __ldg(pos + s1.x), a2 = __ldg(pos + e1.x);
        float2 a3 = __ldg(pos + s2.x), a4 = __ldg(pos + e2.x);
        float2 b1 = __ldg(pos + s1.y), b2 = __ldg(pos + e1.y);
        float2 b3 = __ldg(pos + s2.y), b4 = __ldg(pos + e2.y);
        float2 c1 = __ldg(pos + s1.z), c2 = __ldg(pos + e1.z);
        float2 c3 = __ldg(pos + s2.z), c4 = __ldg(pos + e2.z);
        float2 d1 = __ldg(pos + s1.w), d2 = __ldg(pos + e1.w);
        float2 d3 = __ldg(pos + s2.w), d4 = __ldg(pos + e2.w);

        bool xa = xing_test(a1, a2, a3, a4);
        bool xb = xing_test(b1, b2, b3, b4);
        bool xc = xing_test(c1, c2, c3, c4);
        bool xd = xing_test(d1, d2, d3, d4);

        // batch gather only when crossing (~25% of lanes): fewer L1tex
        // wavefronts; 100KB uint8 table is L1/L2-resident.
        if (xa) atomicAdd(&hist[g_batch8[s1.x]], 1.0f);
        if (xb) atomicAdd(&hist[g_batch8[s1.y]], 1.0f);
        if (xc) atomicAdd(&hist[g_batch8[s1.z]], 1.0f);
        if (xd) atomicAdd(&hist[g_batch8[s1.w]], 1.0f);
    }

    // Scalar tail (P not divisible by 4).
    if (blockIdx.x == 0) {
        for (int p = (P4 << 2) + threadIdx.x; p < P; p += blockDim.x) {
            int s1 = __ldg(epi + p);
            int s2 = __ldg(epi + (size_t)P + p);
            int e1 = __ldg(epi + 2 * (size_t)P + p);
            int e2 = __ldg(epi + 3 * (size_t)P + p);
            if (xing_test(__ldg(pos + s1), __ldg(pos + e1),
                          __ldg(pos + s2), __ldg(pos + e2)))
                atomicAdd(&hist[g_batch8[s1]], 1.0f);
        }
    }

    __syncthreads();
    for (int i = threadIdx.x; i < NUM_GRAPHS; i += blockDim.x) {
        float h = hist[i];
        if (h != 0.0f) atomicAdd(&out[i], h);
    }
}

extern "C" void kernel_launch(void* const* d_in, const int* in_sizes, int n_in,
                              void* d_out, int out_size) {
    // metadata order: node_pos f32[N,2], edge_index i32[2,E] (UNUSED),
    //                 apsp f32[E] (UNUSED), batch_index i32[N],
    //                 edge_pair_index i32[2,2,P]
    const float2* pos = (const float2*)d_in[0];
    const int* batch_index = (const int*)d_in[3];
    const int* epi = (const int*)d_in[4];
    float* out = (float*)d_out;

    int N = in_sizes[0] / 2;
    if (N > 131072) N = 131072;  // scratch-table bound (N is 100000 by spec)
    int P = in_sizes[4] / 4;

    int prep_threads = 256;
    int prep_blocks = (N + prep_threads - 1) / prep_threads;
    prep_kernel<<<prep_blocks, prep_threads>>>(batch_index, out, N);

    int threads = 256;
    int blocks = 148 * 16;  // grid-stride over 4M vec-elements
    crossings_kernel<<<blocks, threads>>>(pos, epi, out, P);
}